// round 14
// baseline (speedup 1.0000x reference)
#include <cuda_runtime.h>
#include <cuda_bf16.h>
#include <math.h>
#include <stdint.h>

// ---------------- problem constants ----------------
#define BATCH   8
#define SEQ     4096
#define DIM     512
#define HEADS   8
#define DHEAD   64
#define WIN     128
#define NWIN    (SEQ / WIN)          // 32
#define NTOK    (BATCH * SEQ)        // 32768
#define QK_SCALE 8.0f
#define LN_EPS   1e-5f
#define FF      (4 * DIM)            // 2048
#define QKVD    (3 * DIM)            // 1536

// ---------------- scratch (device globals; no allocations allowed) --------
__device__ __nv_bfloat16 g_h  [(size_t)NTOK * DIM];   // LN output (bf16)
__device__ float         g_qkv[(size_t)NTOK * QKVD];  // qkv fp32 (rope in place)
__device__ __nv_bfloat16 g_att[(size_t)NTOK * DIM];   // attention output (bf16)
__device__ float         g_x2 [(size_t)NTOK * DIM];   // x after attn residual
__device__ __nv_bfloat16 g_ff1[(size_t)NTOK * FF];    // gelu(...) (bf16)
// bf16 weights: w_qkv | w_out | w_ff1 | w_ff2
#define WR_QKV 0
#define WR_OUT (QKVD * DIM)
#define WR_FF1 (WR_OUT + DIM * DIM)
#define WR_FF2 (WR_FF1 + FF * DIM)
#define WR_TOT (WR_FF2 + DIM * FF)
__device__ __nv_bfloat16 g_wb[WR_TOT];

__device__ __forceinline__ uint32_t packbf(float a, float b) {
    __nv_bfloat162 p = __float22bfloat162_rn(make_float2(a, b));
    return *(uint32_t*)&p;
}

// single-pass weight round: all four weight matrices -> bf16
__global__ void round_all_kernel(const float* __restrict__ w_qkv,
                                 const float* __restrict__ w_out,
                                 const float* __restrict__ w_ff1,
                                 const float* __restrict__ w_ff2,
                                 __nv_bfloat16* __restrict__ dst)
{
    const int i = blockIdx.x * blockDim.x + threadIdx.x;   // float4 index
    if (i >= WR_TOT / 4) return;
    const float* src;
    int off = i;
    if (i < WR_OUT / 4)            { src = w_qkv; }
    else if (i < WR_FF1 / 4)       { src = w_out; off = i - WR_OUT / 4; }
    else if (i < WR_FF2 / 4)       { src = w_ff1; off = i - WR_FF1 / 4; }
    else                           { src = w_ff2; off = i - WR_FF2 / 4; }
    float4 v = ((const float4*)src)[off];
    uint2 o;
    o.x = packbf(v.x, v.y);
    o.y = packbf(v.z, v.w);
    ((uint2*)dst)[i] = o;
}

// inv_freq[l] = 10000^(-2l/64) = 10^(-l/8), correctly-rounded fp32 table
__constant__ float c_invf[32] = {
    1.0f,
    0.7498942093324559f,
    0.5623413251903491f,
    0.4216965034285822f,
    0.31622776601683794f,
    0.23713737056616552f,
    0.17782794100389228f,
    0.1333521432163324f,
    0.1f,
    0.07498942093324559f,
    0.05623413251903491f,
    0.04216965034285822f,
    0.031622776601683794f,
    0.023713737056616552f,
    0.017782794100389228f,
    0.01333521432163324f,
    0.01f,
    0.007498942093324559f,
    0.005623413251903491f,
    0.004216965034285822f,
    0.0031622776601683794f,
    0.0023713737056616552f,
    0.0017782794100389228f,
    0.001333521432163324f,
    0.001f,
    0.0007498942093324559f,
    0.0005623413251903491f,
    0.0004216965034285822f,
    0.00031622776601683794f,
    0.00023713737056616552f,
    0.00017782794100389228f,
    0.0001333521432163324f
};

// ---------------- LayerNorm (bf16 output: feeds GEMM A) ------------------
__global__ void ln_kernel(const float* __restrict__ x,
                          const float* __restrict__ g,
                          const float* __restrict__ b,
                          __nv_bfloat16* __restrict__ out)
{
    __shared__ float ss[4], qq[4];
    const int row = blockIdx.x;
    const int tid = threadIdx.x;           // 128 threads, 1 float4 each
    const float4 v = ((const float4*)(x + (size_t)row * DIM))[tid];

    float s = v.x + v.y + v.z + v.w;
    float q = v.x*v.x + v.y*v.y + v.z*v.z + v.w*v.w;
    #pragma unroll
    for (int o = 16; o; o >>= 1) {
        s += __shfl_xor_sync(0xffffffffu, s, o);
        q += __shfl_xor_sync(0xffffffffu, q, o);
    }
    if ((tid & 31) == 0) { ss[tid >> 5] = s; qq[tid >> 5] = q; }
    __syncthreads();
    s = ss[0] + ss[1] + ss[2] + ss[3];
    q = qq[0] + qq[1] + qq[2] + qq[3];

    const float mean = s * (1.f / DIM);
    const float var  = q * (1.f / DIM) - mean * mean;
    const float inv  = rsqrtf(var + LN_EPS);

    const float4 gg = ((const float4*)g)[tid];
    const float4 bb = ((const float4*)b)[tid];
    uint2 o2;
    o2.x = packbf((v.x - mean) * inv * gg.x + bb.x,
                  (v.y - mean) * inv * gg.y + bb.y);
    o2.y = packbf((v.z - mean) * inv * gg.z + bb.z,
                  (v.w - mean) * inv * gg.w + bb.w);
    ((uint2*)(out + (size_t)row * DIM))[tid] = o2;
}

// ---------------- QK l2-norm + scale + rotary, in place (fp32) -----------
__global__ void __launch_bounds__(256)
qknorm_rope_kernel(float* __restrict__ qkv,
                   const float* __restrict__ qscale,
                   const float* __restrict__ kscale)
{
    const int gw   = (blockIdx.x * blockDim.x + threadIdx.x) >> 5;
    const int lane = threadIdx.x & 31;
    const int head  = gw & 7;
    const int token = gw >> 3;

    float* qb = qkv + (size_t)token * QKVD + head * DHEAD;
    float* kb = qb + DIM;

    const float q1 = qb[lane], q2 = qb[lane + 32];
    const float k1 = kb[lane], k2 = kb[lane + 32];

    float sq = q1 * q1 + q2 * q2;
    float sk = k1 * k1 + k2 * k2;
    #pragma unroll
    for (int o = 16; o; o >>= 1) {
        sq += __shfl_xor_sync(0xffffffffu, sq, o);
        sk += __shfl_xor_sync(0xffffffffu, sk, o);
    }
    const float rq = 1.f / fmaxf(sqrtf(sq), 1e-12f);
    const float rk = 1.f / fmaxf(sqrtf(sk), 1e-12f);

    const float nq1 = q1 * rq * qscale[lane];
    const float nq2 = q2 * rq * qscale[lane + 32];
    const float nk1 = k1 * rk * kscale[lane];
    const float nk2 = k2 * rk * kscale[lane + 32];

    // fp32 angle — matches the reference's own fp32 product rounding
    const float a = (float)(token & (SEQ - 1)) * c_invf[lane];
    float s, c;
    sincosf(a, &s, &c);

    qb[lane]      = nq1 * c - nq2 * s;
    qb[lane + 32] = nq2 * c + nq1 * s;
    kb[lane]      = nk1 * c - nk2 * s;
    kb[lane + 32] = nk2 * c + nk1 * s;
}

// ---------------- packed f32x2 helpers -----------------------------------
__device__ __forceinline__ uint64_t pk2(float a, float b) {
    uint64_t r;
    asm("mov.b64 %0, {%1, %2};" : "=l"(r) : "f"(a), "f"(b));
    return r;
}
__device__ __forceinline__ float2 upk(uint64_t v) {
    float2 r;
    asm("mov.b64 {%0, %1}, %2;" : "=f"(r.x), "=f"(r.y) : "l"(v));
    return r;
}
__device__ __forceinline__ void f2fma(uint64_t& d, uint64_t a, uint64_t b) {
    asm("fma.rn.f32x2 %0, %1, %2, %0;" : "+l"(d) : "l"(a), "l"(b));
}
__device__ __forceinline__ uint64_t f2mul(uint64_t a, uint64_t b) {
    uint64_t d;
    asm("mul.rn.f32x2 %0, %1, %2;" : "=l"(d) : "l"(a), "l"(b));
    return d;
}
__device__ __forceinline__ void lds2(uint64_t& a, uint64_t& b, uint32_t addr) {
    asm volatile("ld.shared.v2.b64 {%0, %1}, [%2];"
                 : "=l"(a), "=l"(b) : "r"(addr));
}

__device__ __forceinline__ uint32_t smem_u32(const void* p) {
    uint32_t a;
    asm("{ .reg .u64 t; cvta.to.shared.u64 t, %1; cvt.u32.u64 %0, t; }"
        : "=r"(a) : "l"(p));
    return a;
}

// ---------------- windowed attention, tiled KV + split, f32x2 -------------
// 256 threads, 2 CTAs/SM. Thread (i, half) owns query i; KV processed one
// 128-key window tile at a time (prev, then cur). q streamed from smem in
// the QK loop (keeps regs under the 128 cap for 2-CTA occupancy).
#define ATTN_SMEM ((128 * 64 * 3) * 4)     // qs + ks + vs = 96 KB
__global__ void __launch_bounds__(256, 2)
attn_kernel(const float* __restrict__ qkv, __nv_bfloat16* __restrict__ out)
{
    extern __shared__ float sm[];
    float* qs = sm;                       // 128*64
    float* ks = sm + 128 * 64;            // 128*64 (row-major [j][d])
    float* vs = ks + 128 * 64;            // 128*64
    float* mg = ks;                       // merge area (reuses ks/vs after sync)

    const int w = blockIdx.x & (NWIN - 1);
    const int h = (blockIdx.x >> 5) & (HEADS - 1);
    const int b = blockIdx.x >> 8;
    const int tid = threadIdx.x;
    const size_t cur = (size_t)b * SEQ + (size_t)w * WIN;

    // stage Q: 2048 float4s, 8 per thread
    #pragma unroll
    for (int t = 0; t < 8; t++) {
        int f = tid + t * 256;
        int row = f >> 4, v = f & 15;
        float4 a = *(const float4*)&qkv[(cur + row) * QKVD + h * DHEAD + v * 4];
        *(float4*)&qs[row * 64 + v * 4] = a;
    }

    const int i    = tid & 127;
    const int half = tid >> 7;
    const uint32_t qaddr = smem_u32(qs) + (uint32_t)i * 256u;
    const uint32_t kbase = smem_u32(ks);
    const uint32_t vbase = smem_u32(vs);

    uint64_t o2[32];
    #pragma unroll
    for (int d = 0; d < 32; d++) o2[d] = 0ull;
    float mval = -1e30f, l = 0.f;

    const int tfirst = (w == 0) ? 1 : 0;
    for (int tile = tfirst; tile < 2; tile++) {
        __syncthreads();                   // prior compute / q staging done
        // stage this tile's K and V (tokens cur-WIN.. or cur..)
        const long tok0 = (long)cur + (tile == 0 ? -(long)WIN : 0);
        #pragma unroll
        for (int t = 0; t < 8; t++) {
            int f = tid + t * 256;         // [0,2048)
            int j = f >> 4, v = f & 15;
            const float* bp = &qkv[(size_t)(tok0 + j) * QKVD + h * DHEAD + v * 4];
            *(float4*)&ks[j * 64 + v * 4] = *(const float4*)(bp + DIM);
            *(float4*)&vs[j * 64 + v * 4] = *(const float4*)(bp + 2 * DIM);
        }
        __syncthreads();

        const int jmax = (tile == 1) ? i : 127;   // causal only in cur tile

        for (int j0 = half * 4; j0 <= jmax; j0 += 8) {
            // ---- scores for keys j0..j0+3 (q streamed from smem) ----
            const uint32_t ka0 = kbase + (uint32_t)(j0 + 0) * 256u;
            const uint32_t ka1 = kbase + (uint32_t)(j0 + 1) * 256u;
            const uint32_t ka2 = kbase + (uint32_t)(j0 + 2) * 256u;
            const uint32_t ka3 = kbase + (uint32_t)(j0 + 3) * 256u;
            uint64_t a0x = 0ull, a0y = 0ull, a1x = 0ull, a1y = 0ull;
            uint64_t a2x = 0ull, a2y = 0ull, a3x = 0ull, a3y = 0ull;
            #pragma unroll
            for (int v = 0; v < 16; v++) {
                uint64_t qx, qy, kx, ky;
                lds2(qx, qy, qaddr + v * 16);
                lds2(kx, ky, ka0 + v * 16);
                f2fma(a0x, qx, kx); f2fma(a0y, qy, ky);
                lds2(kx, ky, ka1 + v * 16);
                f2fma(a1x, qx, kx); f2fma(a1y, qy, ky);
                lds2(kx, ky, ka2 + v * 16);
                f2fma(a2x, qx, kx); f2fma(a2y, qy, ky);
                lds2(kx, ky, ka3 + v * 16);
                f2fma(a3x, qx, kx); f2fma(a3y, qy, ky);
            }
            float s[4];
            {
                const float2 x0 = upk(a0x), y0 = upk(a0y);
                const float2 x1 = upk(a1x), y1 = upk(a1y);
                const float2 x2 = upk(a2x), y2 = upk(a2y);
                const float2 x3 = upk(a3x), y3 = upk(a3y);
                s[0] = ((x0.x + y0.x) + (x0.y + y0.y)) * QK_SCALE;
                s[1] = ((x1.x + y1.x) + (x1.y + y1.y)) * QK_SCALE;
                s[2] = ((x2.x + y2.x) + (x2.y + y2.y)) * QK_SCALE;
                s[3] = ((x3.x + y3.x) + (x3.y + y3.y)) * QK_SCALE;
            }
            if (tile == 1) {
                if (j0 + 1 > jmax) s[1] = -1e30f;
                if (j0 + 2 > jmax) s[2] = -1e30f;
                if (j0 + 3 > jmax) s[3] = -1e30f;
            }

            float nm = fmaxf(fmaxf(s[0], s[1]), fmaxf(s[2], s[3]));
            nm = fmaxf(mval, nm);
            const float corr = __expf(mval - nm);
            const float p0 = __expf(s[0] - nm), p1 = __expf(s[1] - nm);
            const float p2 = __expf(s[2] - nm), p3 = __expf(s[3] - nm);
            l = l * corr + (p0 + p1) + (p2 + p3);
            mval = nm;

            const uint64_t c2  = pk2(corr, corr);
            const uint64_t pp0 = pk2(p0, p0), pp1 = pk2(p1, p1);
            const uint64_t pp2 = pk2(p2, p2), pp3 = pk2(p3, p3);

            const uint32_t va0 = vbase + (uint32_t)(j0 + 0) * 256u;
            const uint32_t va1 = vbase + (uint32_t)(j0 + 1) * 256u;
            const uint32_t va2 = vbase + (uint32_t)(j0 + 2) * 256u;
            const uint32_t va3 = vbase + (uint32_t)(j0 + 3) * 256u;

            #pragma unroll
            for (int v = 0; v < 16; v++) {
                uint64_t x0, y0, x1, y1, x2, y2, x3, y3;
                lds2(x0, y0, va0 + v * 16);
                lds2(x1, y1, va1 + v * 16);
                lds2(x2, y2, va2 + v * 16);
                lds2(x3, y3, va3 + v * 16);
                uint64_t oa = f2mul(o2[2 * v], c2);
                uint64_t ob = f2mul(o2[2 * v + 1], c2);
                f2fma(oa, pp0, x0); f2fma(ob, pp0, y0);
                f2fma(oa, pp1, x1); f2fma(ob, pp1, y1);
                f2fma(oa, pp2, x2); f2fma(ob, pp2, y2);
                f2fma(oa, pp3, x3); f2fma(ob, pp3, y3);
                o2[2 * v] = oa;
                o2[2 * v + 1] = ob;
            }
        }
    }

    // merge halves: half 1 publishes state, half 0 combines + writes
    __syncthreads();                       // all done reading ks/vs
    if (half == 1) {
        float* dst = mg + i * 66;
        dst[0] = mval;
        dst[1] = l;
        #pragma unroll
        for (int d = 0; d < 32; d++) {
            const float2 p = upk(o2[d]);
            dst[2 + 2 * d]     = p.x;
            dst[2 + 2 * d + 1] = p.y;
        }
    }
    __syncthreads();
    if (half == 0) {
        const float* src = mg + i * 66;
        const float m1 = src[0], l1 = src[1];
        const float M  = fmaxf(mval, m1);
        const float e0 = __expf(mval - M);
        const float e1 = __expf(m1 - M);
        const float invL = 1.f / (l * e0 + l1 * e1);

        __nv_bfloat16* op = out + (cur + i) * DIM + h * DHEAD;
        #pragma unroll
        for (int d = 0; d < 64; d += 8) {
            float r[8];
            #pragma unroll
            for (int u = 0; u < 8; u += 2) {
                const float2 p = upk(o2[(d + u) >> 1]);
                r[u]     = (p.x * e0 + src[2 + d + u]     * e1) * invL;
                r[u + 1] = (p.y * e0 + src[2 + d + u + 1] * e1) * invL;
            }
            uint4 uo;
            uo.x = packbf(r[0], r[1]);
            uo.y = packbf(r[2], r[3]);
            uo.z = packbf(r[4], r[5]);
            uo.w = packbf(r[6], r[7]);
            *(uint4*)&op[d] = uo;
        }
    }
}

// =====================================================================
//  BF16 mma.sync GEMM:  C[M,N] = A[M,K] @ W[N,K]^T  (+ epilogue)
//  (unchanged — pinned at mma.sync HMMA-fallback hardware rate)
// =====================================================================

#define BKH       64                        // bf16 elems per K chunk
#define STG_BYTES (128 * 128)               // one operand stage: 16 KB
#define MM_SMEM   (4 * STG_BYTES)           // A0 A1 B0 B1 = 64 KB

__device__ __forceinline__ void ldm4(uint32_t r[4], uint32_t addr) {
    asm volatile("ldmatrix.sync.aligned.m8n8.x4.shared.b16 {%0,%1,%2,%3}, [%4];"
                 : "=r"(r[0]), "=r"(r[1]), "=r"(r[2]), "=r"(r[3]) : "r"(addr));
}

__device__ __forceinline__ void mma_bf16(float c[4], const uint32_t a[4],
                                         uint32_t b0, uint32_t b1)
{
    asm volatile(
        "mma.sync.aligned.m16n8k16.row.col.f32.bf16.bf16.f32 "
        "{%0,%1,%2,%3}, {%4,%5,%6,%7}, {%8,%9}, {%0,%1,%2,%3};"
        : "+f"(c[0]), "+f"(c[1]), "+f"(c[2]), "+f"(c[3])
        : "r"(a[0]), "r"(a[1]), "r"(a[2]), "r"(a[3]), "r"(b0), "r"(b1));
}

// stage one 128xBKH bf16 tile (row-major, ld=K) into swizzled smem stage
__device__ __forceinline__ void stage_bf(const __nv_bfloat16* __restrict__ G,
                                         int K, int row0, int k0, uint32_t sb)
{
    const int t = threadIdx.x;
    #pragma unroll
    for (int i = 0; i < 4; i++) {
        const int idx = i * 256 + t;           // [0,1024)
        const int r = idx >> 3, c = idx & 7;   // 16B col c of row r
        const __nv_bfloat16* src = G + (size_t)(row0 + r) * K + k0 + c * 8;
        const uint32_t dst = sb + (uint32_t)(r * 128 + ((c ^ (r & 7)) << 4));
        asm volatile("cp.async.cg.shared.global [%0], [%1], 16;"
                     :: "r"(dst), "l"(src) : "memory");
    }
}

__device__ __forceinline__ float gelu_exact(float x) {
    return 0.5f * x * (1.f + erff(x * 0.7071067811865476f));
}

template <int EPI, typename TOUT>
__global__ void __launch_bounds__(256)
mm_bf(const __nv_bfloat16* __restrict__ A, const __nv_bfloat16* __restrict__ W,
      const float* __restrict__ bias, const float* __restrict__ res,
      TOUT* __restrict__ C, int M, int N, int K)
{
    extern __shared__ char smc[];
    const uint32_t sb = smem_u32(smc);
    const int tid  = threadIdx.x;
    const int wid  = tid >> 5;
    const int lane = tid & 31;
    const int g    = lane >> 2;
    const int tig  = lane & 3;
    const int wm   = wid & 1;             // 0..1  (M)
    const int wn   = wid >> 1;            // 0..3  (N)
    const int bn   = blockIdx.x * 128;
    const int bm   = blockIdx.y * 128;
    const int NC   = K / BKH;

    // per-thread ldmatrix lane geometry
    const int arow = wm * 64 + (lane & 15);        // +i*16
    const int khA  = lane >> 4;                    // k half (0/1)
    const int sA   = arow & 7;
    const int brow = wn * 32 + (lane & 7) + ((lane >> 4) << 3);  // +jp*16
    const int khB  = (lane >> 3) & 1;
    const int sB   = brow & 7;

    float cfr[4][4][4];
    #pragma unroll
    for (int i = 0; i < 4; i++)
        #pragma unroll
        for (int j = 0; j < 4; j++)
            #pragma unroll
            for (int r = 0; r < 4; r++) cfr[i][j][r] = 0.f;

    stage_bf(A, K, bm, 0, sb);
    stage_bf(W, K, bn, 0, sb + 2 * STG_BYTES);
    asm volatile("cp.async.commit_group;" ::: "memory");

    for (int c = 0; c < NC; ++c) {
        if (c + 1 < NC) {
            const int s = (c + 1) & 1;
            stage_bf(A, K, bm, (c + 1) * BKH, sb + s * STG_BYTES);
            stage_bf(W, K, bn, (c + 1) * BKH, sb + (2 + s) * STG_BYTES);
            asm volatile("cp.async.commit_group;" ::: "memory");
            asm volatile("cp.async.wait_group 1;" ::: "memory");
        } else {
            asm volatile("cp.async.wait_group 0;" ::: "memory");
        }
        __syncthreads();

        const uint32_t Ab = sb + (c & 1) * STG_BYTES;
        const uint32_t Bb = sb + 2 * STG_BYTES + (c & 1) * STG_BYTES;

        #pragma unroll
        for (int ks = 0; ks < 4; ks++) {       // 4 x k16 per 64-elem chunk
            uint32_t af[4][4], bfm[2][4];
            const uint32_t cA = (uint32_t)(((2 * ks + khA) ^ sA) << 4);
            #pragma unroll
            for (int i = 0; i < 4; i++)
                ldm4(af[i], Ab + (uint32_t)((arow + i * 16) * 128) + cA);
            const uint32_t cB = (uint32_t)(((2 * ks + khB) ^ sB) << 4);
            #pragma unroll
            for (int jp = 0; jp < 2; jp++)
                ldm4(bfm[jp], Bb + (uint32_t)((brow + jp * 16) * 128) + cB);

            #pragma unroll
            for (int i = 0; i < 4; i++)
                #pragma unroll
                for (int j = 0; j < 4; j++)
                    mma_bf16(cfr[i][j], af[i],
                             bfm[j >> 1][(j & 1) * 2], bfm[j >> 1][(j & 1) * 2 + 1]);
        }
        __syncthreads();
    }

    // epilogue
    #pragma unroll
    for (int i = 0; i < 4; i++) {
        const int r0 = bm + wm * 64 + i * 16 + g;
        #pragma unroll
        for (int j = 0; j < 4; j++) {
            const int cc = bn + wn * 32 + j * 8 + tig * 2;
            #pragma unroll
            for (int half = 0; half < 2; half++) {
                const int row = r0 + half * 8;
                const size_t base = (size_t)row * N + cc;
                float v0 = cfr[i][j][half * 2 + 0];
                float v1 = cfr[i][j][half * 2 + 1];
                if (EPI == 1) {
                    const float2 rr = *(const float2*)&res[base];
                    const float2 bb = *(const float2*)&bias[cc];
                    v0 += rr.x + bb.x; v1 += rr.y + bb.y;
                }
                if (EPI == 2) {
                    v0 = gelu_exact(v0);
                    v1 = gelu_exact(v1);
                }
                if (EPI == 3) {
                    const float2 rr = *(const float2*)&res[base];
                    v0 += rr.x; v1 += rr.y;
                }
                if constexpr (sizeof(TOUT) == 2) {
                    __nv_bfloat162 p = __float22bfloat162_rn(make_float2(v0, v1));
                    *(__nv_bfloat162*)&C[base] = p;
                } else {
                    *(float2*)&C[base] = make_float2(v0, v1);
                }
            }
        }
    }
}

// ---------------- launch ----------------
extern "C" void kernel_launch(void* const* d_in, const int* in_sizes, int n_in,
                              void* d_out, int out_size)
{
    const float* x       = (const float*)d_in[0];
    const float* w_qkv   = (const float*)d_in[1];
    const float* q_scale = (const float*)d_in[2];
    const float* k_scale = (const float*)d_in[3];
    const float* w_out   = (const float*)d_in[4];
    const float* b_out   = (const float*)d_in[5];
    const float* ln1_g   = (const float*)d_in[6];
    const float* ln1_b   = (const float*)d_in[7];
    const float* ff_ln_g = (const float*)d_in[8];
    const float* ff_ln_b = (const float*)d_in[9];
    const float* w_ff1   = (const float*)d_in[10];
    const float* w_ff2   = (const float*)d_in[11];
    float* out = (float*)d_out;

    __nv_bfloat16 *h, *att, *ff1, *wb;
    float *qkv, *x2;
    cudaGetSymbolAddress((void**)&h,   g_h);
    cudaGetSymbolAddress((void**)&qkv, g_qkv);
    cudaGetSymbolAddress((void**)&att, g_att);
    cudaGetSymbolAddress((void**)&x2,  g_x2);
    cudaGetSymbolAddress((void**)&ff1, g_ff1);
    cudaGetSymbolAddress((void**)&wb,  g_wb);

    cudaFuncSetAttribute(attn_kernel,
                         cudaFuncAttributeMaxDynamicSharedMemorySize, ATTN_SMEM);
    cudaFuncSetAttribute(mm_bf<0, float>, cudaFuncAttributeMaxDynamicSharedMemorySize, MM_SMEM);
    cudaFuncSetAttribute(mm_bf<1, float>, cudaFuncAttributeMaxDynamicSharedMemorySize, MM_SMEM);
    cudaFuncSetAttribute(mm_bf<2, __nv_bfloat16>, cudaFuncAttributeMaxDynamicSharedMemorySize, MM_SMEM);
    cudaFuncSetAttribute(mm_bf<3, float>, cudaFuncAttributeMaxDynamicSharedMemorySize, MM_SMEM);

    // 0) weight prepass: round to bf16 (single launch)
    round_all_kernel<<<(WR_TOT / 4 + 255) / 256, 256>>>(w_qkv, w_out, w_ff1, w_ff2, wb);

    // 1) h = bf16(LN(x))
    ln_kernel<<<NTOK, 128>>>(x, ln1_g, ln1_b, h);
    // 2) qkv = h @ w_qkv^T   (fp32 out)
    mm_bf<0, float><<<dim3(QKVD / 128, NTOK / 128), 256, MM_SMEM>>>(
        h, wb + WR_QKV, nullptr, nullptr, qkv, NTOK, QKVD, DIM);
    // 3) q,k: l2norm * scale, rotary (in place, fp32; 1 warp per token-head)
    qknorm_rope_kernel<<<(NTOK * HEADS) / 8, 256>>>(qkv, q_scale, k_scale);
    // 4) windowed attention (f32x2, tiled KV, 2 CTAs/SM)
    attn_kernel<<<BATCH * HEADS * NWIN, 256, ATTN_SMEM>>>(qkv, att);
    // 5) x2 = x + att @ w_out^T + b_out
    mm_bf<1, float><<<dim3(DIM / 128, NTOK / 128), 256, MM_SMEM>>>(
        att, wb + WR_OUT, b_out, x, x2, NTOK, DIM, DIM);
    // 6) h = bf16(LN(x2))
    ln_kernel<<<NTOK, 128>>>(x2, ff_ln_g, ff_ln_b, h);
    // 7) ff1 = bf16(gelu(h @ w_ff1^T))
    mm_bf<2, __nv_bfloat16><<<dim3(FF / 128, NTOK / 128), 256, MM_SMEM>>>(
        h, wb + WR_FF1, nullptr, nullptr, ff1, NTOK, FF, DIM);
    // 8) out = x2 + ff1 @ w_ff2^T
    mm_bf<3, float><<<dim3(DIM / 128, NTOK / 128), 256, MM_SMEM>>>(
        ff1, wb + WR_FF2, nullptr, x2, out, NTOK, DIM, FF);
}

// round 15
// speedup vs baseline: 1.4920x; 1.4920x over previous
#include <cuda_runtime.h>
#include <cuda_bf16.h>
#include <math.h>
#include <stdint.h>

// ---------------- problem constants ----------------
#define BATCH   8
#define SEQ     4096
#define DIM     512
#define HEADS   8
#define DHEAD   64
#define WIN     128
#define NWIN    (SEQ / WIN)          // 32
#define NTOK    (BATCH * SEQ)        // 32768
#define QK_SCALE 8.0f
#define LN_EPS   1e-5f
#define FF      (4 * DIM)            // 2048
#define QKVD    (3 * DIM)            // 1536

// ---------------- scratch (device globals; no allocations allowed) --------
__device__ __nv_bfloat16 g_h  [(size_t)NTOK * DIM];   // LN output (bf16)
__device__ float         g_qkv[(size_t)NTOK * QKVD];  // qkv fp32 (rope in place)
__device__ __nv_bfloat16 g_att[(size_t)NTOK * DIM];   // attention output (bf16)
__device__ float         g_x2 [(size_t)NTOK * DIM];   // x after attn residual
__device__ __nv_bfloat16 g_ff1[(size_t)NTOK * FF];    // gelu(...) (bf16)
// bf16 weights: w_qkv | w_out | w_ff1 | w_ff2
#define WR_QKV 0
#define WR_OUT (QKVD * DIM)
#define WR_FF1 (WR_OUT + DIM * DIM)
#define WR_FF2 (WR_FF1 + FF * DIM)
#define WR_TOT (WR_FF2 + DIM * FF)
__device__ __nv_bfloat16 g_wb[WR_TOT];

__device__ __forceinline__ uint32_t packbf(float a, float b) {
    __nv_bfloat162 p = __float22bfloat162_rn(make_float2(a, b));
    return *(uint32_t*)&p;
}

// single-pass weight round: all four weight matrices -> bf16
__global__ void round_all_kernel(const float* __restrict__ w_qkv,
                                 const float* __restrict__ w_out,
                                 const float* __restrict__ w_ff1,
                                 const float* __restrict__ w_ff2,
                                 __nv_bfloat16* __restrict__ dst)
{
    const int i = blockIdx.x * blockDim.x + threadIdx.x;   // float4 index
    if (i >= WR_TOT / 4) return;
    const float* src;
    int off = i;
    if (i < WR_OUT / 4)            { src = w_qkv; }
    else if (i < WR_FF1 / 4)       { src = w_out; off = i - WR_OUT / 4; }
    else if (i < WR_FF2 / 4)       { src = w_ff1; off = i - WR_FF1 / 4; }
    else                           { src = w_ff2; off = i - WR_FF2 / 4; }
    float4 v = ((const float4*)src)[off];
    uint2 o;
    o.x = packbf(v.x, v.y);
    o.y = packbf(v.z, v.w);
    ((uint2*)dst)[i] = o;
}

// inv_freq[l] = 10000^(-2l/64) = 10^(-l/8), correctly-rounded fp32 table
__constant__ float c_invf[32] = {
    1.0f,
    0.7498942093324559f,
    0.5623413251903491f,
    0.4216965034285822f,
    0.31622776601683794f,
    0.23713737056616552f,
    0.17782794100389228f,
    0.1333521432163324f,
    0.1f,
    0.07498942093324559f,
    0.05623413251903491f,
    0.04216965034285822f,
    0.031622776601683794f,
    0.023713737056616552f,
    0.017782794100389228f,
    0.01333521432163324f,
    0.01f,
    0.007498942093324559f,
    0.005623413251903491f,
    0.004216965034285822f,
    0.0031622776601683794f,
    0.0023713737056616552f,
    0.0017782794100389228f,
    0.001333521432163324f,
    0.001f,
    0.0007498942093324559f,
    0.0005623413251903491f,
    0.0004216965034285822f,
    0.00031622776601683794f,
    0.00023713737056616552f,
    0.00017782794100389228f,
    0.0001333521432163324f
};

// ---------------- LayerNorm (bf16 output: feeds GEMM A) ------------------
__global__ void ln_kernel(const float* __restrict__ x,
                          const float* __restrict__ g,
                          const float* __restrict__ b,
                          __nv_bfloat16* __restrict__ out)
{
    __shared__ float ss[4], qq[4];
    const int row = blockIdx.x;
    const int tid = threadIdx.x;           // 128 threads, 1 float4 each
    const float4 v = ((const float4*)(x + (size_t)row * DIM))[tid];

    float s = v.x + v.y + v.z + v.w;
    float q = v.x*v.x + v.y*v.y + v.z*v.z + v.w*v.w;
    #pragma unroll
    for (int o = 16; o; o >>= 1) {
        s += __shfl_xor_sync(0xffffffffu, s, o);
        q += __shfl_xor_sync(0xffffffffu, q, o);
    }
    if ((tid & 31) == 0) { ss[tid >> 5] = s; qq[tid >> 5] = q; }
    __syncthreads();
    s = ss[0] + ss[1] + ss[2] + ss[3];
    q = qq[0] + qq[1] + qq[2] + qq[3];

    const float mean = s * (1.f / DIM);
    const float var  = q * (1.f / DIM) - mean * mean;
    const float inv  = rsqrtf(var + LN_EPS);

    const float4 gg = ((const float4*)g)[tid];
    const float4 bb = ((const float4*)b)[tid];
    uint2 o2;
    o2.x = packbf((v.x - mean) * inv * gg.x + bb.x,
                  (v.y - mean) * inv * gg.y + bb.y);
    o2.y = packbf((v.z - mean) * inv * gg.z + bb.z,
                  (v.w - mean) * inv * gg.w + bb.w);
    ((uint2*)(out + (size_t)row * DIM))[tid] = o2;
}

// ---------------- QK l2-norm + scale + rotary, in place (fp32) -----------
// One warp handles TWO adjacent (token, head) units: 2g and 2g+1 always
// share the same token, so one sincos serves both heads. MLP=8.
__global__ void __launch_bounds__(256)
qknorm_rope_kernel(float* __restrict__ qkv,
                   const float* __restrict__ qscale,
                   const float* __restrict__ kscale)
{
    const int gw   = (blockIdx.x * blockDim.x + threadIdx.x) >> 5;
    const int lane = threadIdx.x & 31;
    const int u0    = gw * 2;             // unit 0
    const int head0 = u0 & 7;             // unit 1 = same token, head0+1
    const int token = u0 >> 3;

    float* qa = qkv + (size_t)token * QKVD + head0 * DHEAD;
    float* ka = qa + DIM;
    float* qb = qa + DHEAD;
    float* kb = ka + DHEAD;

    const float qa1 = qa[lane], qa2 = qa[lane + 32];
    const float ka1 = ka[lane], ka2 = ka[lane + 32];
    const float qb1 = qb[lane], qb2 = qb[lane + 32];
    const float kb1 = kb[lane], kb2 = kb[lane + 32];

    float sqa = qa1 * qa1 + qa2 * qa2;
    float ska = ka1 * ka1 + ka2 * ka2;
    float sqb = qb1 * qb1 + qb2 * qb2;
    float skb = kb1 * kb1 + kb2 * kb2;
    #pragma unroll
    for (int o = 16; o; o >>= 1) {
        sqa += __shfl_xor_sync(0xffffffffu, sqa, o);
        ska += __shfl_xor_sync(0xffffffffu, ska, o);
        sqb += __shfl_xor_sync(0xffffffffu, sqb, o);
        skb += __shfl_xor_sync(0xffffffffu, skb, o);
    }
    const float rqa = 1.f / fmaxf(sqrtf(sqa), 1e-12f);
    const float rka = 1.f / fmaxf(sqrtf(ska), 1e-12f);
    const float rqb = 1.f / fmaxf(sqrtf(sqb), 1e-12f);
    const float rkb = 1.f / fmaxf(sqrtf(skb), 1e-12f);

    const float qs1 = qscale[lane], qs2 = qscale[lane + 32];
    const float ks1 = kscale[lane], ks2 = kscale[lane + 32];

    const float nqa1 = qa1 * rqa * qs1, nqa2 = qa2 * rqa * qs2;
    const float nka1 = ka1 * rka * ks1, nka2 = ka2 * rka * ks2;
    const float nqb1 = qb1 * rqb * qs1, nqb2 = qb2 * rqb * qs2;
    const float nkb1 = kb1 * rkb * ks1, nkb2 = kb2 * rkb * ks2;

    // fp32 angle — matches the reference's own fp32 product rounding
    const float a = (float)(token & (SEQ - 1)) * c_invf[lane];
    float s, c;
    sincosf(a, &s, &c);

    qa[lane]      = nqa1 * c - nqa2 * s;
    qa[lane + 32] = nqa2 * c + nqa1 * s;
    ka[lane]      = nka1 * c - nka2 * s;
    ka[lane + 32] = nka2 * c + nka1 * s;
    qb[lane]      = nqb1 * c - nqb2 * s;
    qb[lane + 32] = nqb2 * c + nqb1 * s;
    kb[lane]      = nkb1 * c - nkb2 * s;
    kb[lane + 32] = nkb2 * c + nkb1 * s;
}

// ---------------- packed f32x2 helpers -----------------------------------
__device__ __forceinline__ uint64_t pk2(float a, float b) {
    uint64_t r;
    asm("mov.b64 %0, {%1, %2};" : "=l"(r) : "f"(a), "f"(b));
    return r;
}
__device__ __forceinline__ float2 upk(uint64_t v) {
    float2 r;
    asm("mov.b64 {%0, %1}, %2;" : "=f"(r.x), "=f"(r.y) : "l"(v));
    return r;
}
__device__ __forceinline__ void f2fma(uint64_t& d, uint64_t a, uint64_t b) {
    asm("fma.rn.f32x2 %0, %1, %2, %0;" : "+l"(d) : "l"(a), "l"(b));
}
__device__ __forceinline__ uint64_t f2mul(uint64_t a, uint64_t b) {
    uint64_t d;
    asm("mul.rn.f32x2 %0, %1, %2;" : "=l"(d) : "l"(a), "l"(b));
    return d;
}
__device__ __forceinline__ void lds2(uint64_t& a, uint64_t& b, uint32_t addr) {
    asm volatile("ld.shared.v2.b64 {%0, %1}, [%2];"
                 : "=l"(a), "=l"(b) : "r"(addr));
}

__device__ __forceinline__ uint32_t smem_u32(const void* p) {
    uint32_t a;
    asm("{ .reg .u64 t; cvta.to.shared.u64 t, %1; cvt.u32.u64 %0, t; }"
        : "=r"(a) : "l"(p));
    return a;
}

// ---------------- windowed attention, split-KV, packed f32x2 --------------
// (R12 version restored — q resident in registers, single 256-key KV stage,
//  160 KB smem, 1 CTA/SM, no launch-bounds reg cap.)
__global__ void __launch_bounds__(256, 1)
attn_kernel(const float* __restrict__ qkv, __nv_bfloat16* __restrict__ out)
{
    extern __shared__ float sm[];
    float* qs = sm;                       // 128*64
    float* ks = sm + 128 * 64;            // 256*64 (row-major [j][d])
    float* vs = ks + 256 * 64;            // 256*64
    float* mg = ks;                       // merge area (reuses ks after sync)

    const int w = blockIdx.x & (NWIN - 1);
    const int h = (blockIdx.x >> 5) & (HEADS - 1);
    const int b = blockIdx.x >> 8;
    const int tid = threadIdx.x;
    const size_t cur = (size_t)b * SEQ + (size_t)w * WIN;

    // stage Q: 2048 float4s, 8 per thread
    #pragma unroll
    for (int t = 0; t < 8; t++) {
        int f = tid + t * 256;
        int row = f >> 4, v = f & 15;
        float4 a = *(const float4*)&qkv[(cur + row) * QKVD + h * DHEAD + v * 4];
        *(float4*)&qs[row * 64 + v * 4] = a;
    }
    // stage K and V (row-major): 4096 float4s, 16 per thread
    #pragma unroll
    for (int t = 0; t < 16; t++) {
        int f = tid + t * 256;
        int j = f >> 4, v = f & 15;
        float4 k4 = make_float4(0.f, 0.f, 0.f, 0.f);
        float4 v4 = make_float4(0.f, 0.f, 0.f, 0.f);
        if (j >= WIN || w > 0) {
            const float* bp = &qkv[(cur + j - WIN) * QKVD + h * DHEAD + v * 4];
            k4 = *(const float4*)(bp + DIM);
            v4 = *(const float4*)(bp + 2 * DIM);
        }
        *(float4*)&ks[j * 64 + v * 4] = k4;
        *(float4*)&vs[j * 64 + v * 4] = v4;
    }
    __syncthreads();

    const int i    = tid & 127;
    const int half = tid >> 7;

    // load q as 32 packed f32x2
    uint64_t q2[32];
    {
        const uint32_t qaddr = smem_u32(&qs[i * 64]);
        #pragma unroll
        for (int v = 0; v < 16; v++)
            lds2(q2[2 * v], q2[2 * v + 1], qaddr + v * 16);
    }

    uint64_t o2[32];
    #pragma unroll
    for (int d = 0; d < 32; d++) o2[d] = 0ull;
    float mval = -1e30f, l = 0.f;

    const uint32_t kbase = smem_u32(ks);
    const uint32_t vbase = smem_u32(vs);

    const int jstart = ((w == 0) ? WIN : 0) + half * 4;
    const int jend   = i + WIN;           // inclusive; causal inside window

    for (int j0 = jstart; j0 <= jend; j0 += 8) {
        // ---- scores for keys j0..j0+3 (packed dot products) ----
        float s[4];
        #pragma unroll
        for (int jj = 0; jj < 4; jj++) {
            const uint32_t ka = kbase + (uint32_t)(j0 + jj) * 256u;
            uint64_t a0 = 0ull, a1 = 0ull;
            #pragma unroll
            for (int v = 0; v < 16; v++) {
                uint64_t kx, ky;
                lds2(kx, ky, ka + v * 16);
                f2fma(a0, q2[2 * v], kx);
                f2fma(a1, q2[2 * v + 1], ky);
            }
            const float2 x0 = upk(a0), x1 = upk(a1);
            s[jj] = ((x0.x + x1.x) + (x0.y + x1.y)) * QK_SCALE;
        }
        if (j0 + 1 > jend) s[1] = -1e30f;
        if (j0 + 2 > jend) s[2] = -1e30f;
        if (j0 + 3 > jend) s[3] = -1e30f;

        float nm = fmaxf(fmaxf(s[0], s[1]), fmaxf(s[2], s[3]));
        nm = fmaxf(mval, nm);
        const float corr = __expf(mval - nm);
        const float p0 = __expf(s[0] - nm), p1 = __expf(s[1] - nm);
        const float p2 = __expf(s[2] - nm), p3 = __expf(s[3] - nm);
        l = l * corr + (p0 + p1) + (p2 + p3);
        mval = nm;

        const uint64_t c2  = pk2(corr, corr);
        const uint64_t pp0 = pk2(p0, p0), pp1 = pk2(p1, p1);
        const uint64_t pp2 = pk2(p2, p2), pp3 = pk2(p3, p3);

        const uint32_t va0 = vbase + (uint32_t)(j0 + 0) * 256u;
        const uint32_t va1 = vbase + (uint32_t)(j0 + 1) * 256u;
        const uint32_t va2 = vbase + (uint32_t)(j0 + 2) * 256u;
        const uint32_t va3 = vbase + (uint32_t)(j0 + 3) * 256u;

        #pragma unroll
        for (int v = 0; v < 16; v++) {
            uint64_t x0, y0, x1, y1, x2, y2, x3, y3;
            lds2(x0, y0, va0 + v * 16);
            lds2(x1, y1, va1 + v * 16);
            lds2(x2, y2, va2 + v * 16);
            lds2(x3, y3, va3 + v * 16);
            uint64_t oa = f2mul(o2[2 * v], c2);
            uint64_t ob = f2mul(o2[2 * v + 1], c2);
            f2fma(oa, pp0, x0); f2fma(ob, pp0, y0);
            f2fma(oa, pp1, x1); f2fma(ob, pp1, y1);
            f2fma(oa, pp2, x2); f2fma(ob, pp2, y2);
            f2fma(oa, pp3, x3); f2fma(ob, pp3, y3);
            o2[2 * v] = oa;
            o2[2 * v + 1] = ob;
        }
    }

    // merge halves: half 1 publishes state, half 0 combines + writes
    __syncthreads();                       // all done reading ks/vs
    if (half == 1) {
        float* dst = mg + i * 66;
        dst[0] = mval;
        dst[1] = l;
        #pragma unroll
        for (int d = 0; d < 32; d++) {
            const float2 p = upk(o2[d]);
            dst[2 + 2 * d]     = p.x;
            dst[2 + 2 * d + 1] = p.y;
        }
    }
    __syncthreads();
    if (half == 0) {
        const float* src = mg + i * 66;
        const float m1 = src[0], l1 = src[1];
        const float M  = fmaxf(mval, m1);
        const float e0 = __expf(mval - M);
        const float e1 = __expf(m1 - M);
        const float invL = 1.f / (l * e0 + l1 * e1);

        __nv_bfloat16* op = out + (cur + i) * DIM + h * DHEAD;
        #pragma unroll
        for (int d = 0; d < 64; d += 8) {
            float r[8];
            #pragma unroll
            for (int u = 0; u < 8; u += 2) {
                const float2 p = upk(o2[(d + u) >> 1]);
                r[u]     = (p.x * e0 + src[2 + d + u]     * e1) * invL;
                r[u + 1] = (p.y * e0 + src[2 + d + u + 1] * e1) * invL;
            }
            uint4 uo;
            uo.x = packbf(r[0], r[1]);
            uo.y = packbf(r[2], r[3]);
            uo.z = packbf(r[4], r[5]);
            uo.w = packbf(r[6], r[7]);
            *(uint4*)&op[d] = uo;
        }
    }
}

// =====================================================================
//  BF16 mma.sync GEMM:  C[M,N] = A[M,K] @ W[N,K]^T  (+ epilogue)
//  (unchanged — pinned at mma.sync HMMA-fallback hardware rate)
// =====================================================================

#define BKH       64                        // bf16 elems per K chunk
#define STG_BYTES (128 * 128)               // one operand stage: 16 KB
#define MM_SMEM   (4 * STG_BYTES)           // A0 A1 B0 B1 = 64 KB

__device__ __forceinline__ void ldm4(uint32_t r[4], uint32_t addr) {
    asm volatile("ldmatrix.sync.aligned.m8n8.x4.shared.b16 {%0,%1,%2,%3}, [%4];"
                 : "=r"(r[0]), "=r"(r[1]), "=r"(r[2]), "=r"(r[3]) : "r"(addr));
}

__device__ __forceinline__ void mma_bf16(float c[4], const uint32_t a[4],
                                         uint32_t b0, uint32_t b1)
{
    asm volatile(
        "mma.sync.aligned.m16n8k16.row.col.f32.bf16.bf16.f32 "
        "{%0,%1,%2,%3}, {%4,%5,%6,%7}, {%8,%9}, {%0,%1,%2,%3};"
        : "+f"(c[0]), "+f"(c[1]), "+f"(c[2]), "+f"(c[3])
        : "r"(a[0]), "r"(a[1]), "r"(a[2]), "r"(a[3]), "r"(b0), "r"(b1));
}

// stage one 128xBKH bf16 tile (row-major, ld=K) into swizzled smem stage
__device__ __forceinline__ void stage_bf(const __nv_bfloat16* __restrict__ G,
                                         int K, int row0, int k0, uint32_t sb)
{
    const int t = threadIdx.x;
    #pragma unroll
    for (int i = 0; i < 4; i++) {
        const int idx = i * 256 + t;           // [0,1024)
        const int r = idx >> 3, c = idx & 7;   // 16B col c of row r
        const __nv_bfloat16* src = G + (size_t)(row0 + r) * K + k0 + c * 8;
        const uint32_t dst = sb + (uint32_t)(r * 128 + ((c ^ (r & 7)) << 4));
        asm volatile("cp.async.cg.shared.global [%0], [%1], 16;"
                     :: "r"(dst), "l"(src) : "memory");
    }
}

__device__ __forceinline__ float gelu_exact(float x) {
    return 0.5f * x * (1.f + erff(x * 0.7071067811865476f));
}

template <int EPI, typename TOUT>
__global__ void __launch_bounds__(256)
mm_bf(const __nv_bfloat16* __restrict__ A, const __nv_bfloat16* __restrict__ W,
      const float* __restrict__ bias, const float* __restrict__ res,
      TOUT* __restrict__ C, int M, int N, int K)
{
    extern __shared__ char smc[];
    const uint32_t sb = smem_u32(smc);
    const int tid  = threadIdx.x;
    const int wid  = tid >> 5;
    const int lane = tid & 31;
    const int g    = lane >> 2;
    const int tig  = lane & 3;
    const int wm   = wid & 1;             // 0..1  (M)
    const int wn   = wid >> 1;            // 0..3  (N)
    const int bn   = blockIdx.x * 128;
    const int bm   = blockIdx.y * 128;
    const int NC   = K / BKH;

    // per-thread ldmatrix lane geometry
    const int arow = wm * 64 + (lane & 15);        // +i*16
    const int khA  = lane >> 4;                    // k half (0/1)
    const int sA   = arow & 7;
    const int brow = wn * 32 + (lane & 7) + ((lane >> 4) << 3);  // +jp*16
    const int khB  = (lane >> 3) & 1;
    const int sB   = brow & 7;

    float cfr[4][4][4];
    #pragma unroll
    for (int i = 0; i < 4; i++)
        #pragma unroll
        for (int j = 0; j < 4; j++)
            #pragma unroll
            for (int r = 0; r < 4; r++) cfr[i][j][r] = 0.f;

    stage_bf(A, K, bm, 0, sb);
    stage_bf(W, K, bn, 0, sb + 2 * STG_BYTES);
    asm volatile("cp.async.commit_group;" ::: "memory");

    for (int c = 0; c < NC; ++c) {
        if (c + 1 < NC) {
            const int s = (c + 1) & 1;
            stage_bf(A, K, bm, (c + 1) * BKH, sb + s * STG_BYTES);
            stage_bf(W, K, bn, (c + 1) * BKH, sb + (2 + s) * STG_BYTES);
            asm volatile("cp.async.commit_group;" ::: "memory");
            asm volatile("cp.async.wait_group 1;" ::: "memory");
        } else {
            asm volatile("cp.async.wait_group 0;" ::: "memory");
        }
        __syncthreads();

        const uint32_t Ab = sb + (c & 1) * STG_BYTES;
        const uint32_t Bb = sb + 2 * STG_BYTES + (c & 1) * STG_BYTES;

        #pragma unroll
        for (int ks = 0; ks < 4; ks++) {       // 4 x k16 per 64-elem chunk
            uint32_t af[4][4], bfm[2][4];
            const uint32_t cA = (uint32_t)(((2 * ks + khA) ^ sA) << 4);
            #pragma unroll
            for (int i = 0; i < 4; i++)
                ldm4(af[i], Ab + (uint32_t)((arow + i * 16) * 128) + cA);
            const uint32_t cB = (uint32_t)(((2 * ks + khB) ^ sB) << 4);
            #pragma unroll
            for (int jp = 0; jp < 2; jp++)
                ldm4(bfm[jp], Bb + (uint32_t)((brow + jp * 16) * 128) + cB);

            #pragma unroll
            for (int i = 0; i < 4; i++)
                #pragma unroll
                for (int j = 0; j < 4; j++)
                    mma_bf16(cfr[i][j], af[i],
                             bfm[j >> 1][(j & 1) * 2], bfm[j >> 1][(j & 1) * 2 + 1]);
        }
        __syncthreads();
    }

    // epilogue
    #pragma unroll
    for (int i = 0; i < 4; i++) {
        const int r0 = bm + wm * 64 + i * 16 + g;
        #pragma unroll
        for (int j = 0; j < 4; j++) {
            const int cc = bn + wn * 32 + j * 8 + tig * 2;
            #pragma unroll
            for (int half = 0; half < 2; half++) {
                const int row = r0 + half * 8;
                const size_t base = (size_t)row * N + cc;
                float v0 = cfr[i][j][half * 2 + 0];
                float v1 = cfr[i][j][half * 2 + 1];
                if (EPI == 1) {
                    const float2 rr = *(const float2*)&res[base];
                    const float2 bb = *(const float2*)&bias[cc];
                    v0 += rr.x + bb.x; v1 += rr.y + bb.y;
                }
                if (EPI == 2) {
                    v0 = gelu_exact(v0);
                    v1 = gelu_exact(v1);
                }
                if (EPI == 3) {
                    const float2 rr = *(const float2*)&res[base];
                    v0 += rr.x; v1 += rr.y;
                }
                if constexpr (sizeof(TOUT) == 2) {
                    __nv_bfloat162 p = __float22bfloat162_rn(make_float2(v0, v1));
                    *(__nv_bfloat162*)&C[base] = p;
                } else {
                    *(float2*)&C[base] = make_float2(v0, v1);
                }
            }
        }
    }
}

// ---------------- launch ----------------
extern "C" void kernel_launch(void* const* d_in, const int* in_sizes, int n_in,
                              void* d_out, int out_size)
{
    const float* x       = (const float*)d_in[0];
    const float* w_qkv   = (const float*)d_in[1];
    const float* q_scale = (const float*)d_in[2];
    const float* k_scale = (const float*)d_in[3];
    const float* w_out   = (const float*)d_in[4];
    const float* b_out   = (const float*)d_in[5];
    const float* ln1_g   = (const float*)d_in[6];
    const float* ln1_b   = (const float*)d_in[7];
    const float* ff_ln_g = (const float*)d_in[8];
    const float* ff_ln_b = (const float*)d_in[9];
    const float* w_ff1   = (const float*)d_in[10];
    const float* w_ff2   = (const float*)d_in[11];
    float* out = (float*)d_out;

    __nv_bfloat16 *h, *att, *ff1, *wb;
    float *qkv, *x2;
    cudaGetSymbolAddress((void**)&h,   g_h);
    cudaGetSymbolAddress((void**)&qkv, g_qkv);
    cudaGetSymbolAddress((void**)&att, g_att);
    cudaGetSymbolAddress((void**)&x2,  g_x2);
    cudaGetSymbolAddress((void**)&ff1, g_ff1);
    cudaGetSymbolAddress((void**)&wb,  g_wb);

    const int ATTN_SMEM = (128 * 64 + 256 * 64 + 256 * 64) * 4;   // 160 KB
    cudaFuncSetAttribute(attn_kernel,
                         cudaFuncAttributeMaxDynamicSharedMemorySize, ATTN_SMEM);
    cudaFuncSetAttribute(mm_bf<0, float>, cudaFuncAttributeMaxDynamicSharedMemorySize, MM_SMEM);
    cudaFuncSetAttribute(mm_bf<1, float>, cudaFuncAttributeMaxDynamicSharedMemorySize, MM_SMEM);
    cudaFuncSetAttribute(mm_bf<2, __nv_bfloat16>, cudaFuncAttributeMaxDynamicSharedMemorySize, MM_SMEM);
    cudaFuncSetAttribute(mm_bf<3, float>, cudaFuncAttributeMaxDynamicSharedMemorySize, MM_SMEM);

    // 0) weight prepass: round to bf16 (single launch)
    round_all_kernel<<<(WR_TOT / 4 + 255) / 256, 256>>>(w_qkv, w_out, w_ff1, w_ff2, wb);

    // 1) h = bf16(LN(x))
    ln_kernel<<<NTOK, 128>>>(x, ln1_g, ln1_b, h);
    // 2) qkv = h @ w_qkv^T   (fp32 out)
    mm_bf<0, float><<<dim3(QKVD / 128, NTOK / 128), 256, MM_SMEM>>>(
        h, wb + WR_QKV, nullptr, nullptr, qkv, NTOK, QKVD, DIM);
    // 3) q,k: l2norm * scale, rotary (2 heads per warp, shared sincos)
    qknorm_rope_kernel<<<(NTOK * HEADS) / 16, 256>>>(qkv, q_scale, k_scale);
    // 4) windowed attention (packed f32x2, bf16 out, split-KV 256 threads)
    attn_kernel<<<BATCH * HEADS * NWIN, 256, ATTN_SMEM>>>(qkv, att);
    // 5) x2 = x + att @ w_out^T + b_out
    mm_bf<1, float><<<dim3(DIM / 128, NTOK / 128), 256, MM_SMEM>>>(
        att, wb + WR_OUT, b_out, x, x2, NTOK, DIM, DIM);
    // 6) h = bf16(LN(x2))
    ln_kernel<<<NTOK, 128>>>(x2, ff_ln_g, ff_ln_b, h);
    // 7) ff1 = bf16(gelu(h @ w_ff1^T))
    mm_bf<2, __nv_bfloat16><<<dim3(FF / 128, NTOK / 128), 256, MM_SMEM>>>(
        h, wb + WR_FF1, nullptr, nullptr, ff1, NTOK, FF, DIM);
    // 8) out = x2 + ff1 @ w_ff2^T
    mm_bf<3, float><<<dim3(DIM / 128, NTOK / 128), 256, MM_SMEM>>>(
        ff1, wb + WR_FF2, nullptr, x2, out, NTOK, DIM, FF);
}